// round 2
// baseline (speedup 1.0000x reference)
#include <cuda_runtime.h>
#include <float.h>

#define Bb 4
#define Cc 256
#define C8 32
#define Hh 64
#define Ww 64
#define HW 4096

typedef unsigned long long ull;

// ---------------- f32x2 helpers (sm_103a packed dual-FP32) -----------------
__device__ __forceinline__ ull pack2(float lo, float hi) {
    ull r;
    asm("mov.b64 %0, {%1, %2};" : "=l"(r) : "f"(lo), "f"(hi));
    return r;
}
__device__ __forceinline__ void fma2(ull& d, ull a, ull b) {
    asm("fma.rn.f32x2 %0, %1, %2, %0;" : "+l"(d) : "l"(a), "l"(b));
}
__device__ __forceinline__ void unpack2(ull v, float& lo, float& hi) {
    asm("mov.b64 {%0, %1}, %2;" : "=f"(lo), "=f"(hi) : "l"(v));
}

// ---------------- scratch (static device arrays; no runtime allocation) ----
__device__ float g_q[Bb * C8 * HW];           // 2 MB
__device__ float g_k[Bb * C8 * HW];           // 2 MB
__device__ float g_v[Bb * Cc * HW];           // 16 MB
__device__ float g_T[Bb * Cc * HW];           // 16 MB
__device__ float g_Wt[2 * Cc * 9 * Cc];       // 4.7 MB  (I=512,3,3,O=256)
__device__ float g_pmax[Bb * 4 * HW];
__device__ int   g_parg[Bb * 4 * HW];
__device__ float g_S[Bb * HW];
__device__ int   g_arg[Bb * HW];

// ---------------- 0) weight transpose: Wf(O=256,I=512,3,3) -> Wt(I,3,3,O) ---
__global__ void transpose_wf(const float* __restrict__ Wf) {
    int t = blockIdx.x * 256 + threadIdx.x;       // 512*9*256 = 1,179,648
    if (t >= 512 * 9 * 256) return;
    int o = t & 255;
    int k = (t >> 8) % 9;
    int i = t / (256 * 9);
    g_Wt[t] = Wf[((size_t)o * 512 + i) * 9 + k];
}

// ---------------- 1) 1x1-conv GEMM: out[b,o,hw] = W[o,:]@x[b,:,hw]+bias ----
// tile: 32 o x 128 hw per block, 256 threads, thread tile 4o x 4hw CONTIGUOUS
// inner loop: 1 broadcast LDS.128 (W) + 1 conflict-free LDS.128 (X) / 16 FFMA
__global__ __launch_bounds__(256) void gemm1x1(const float* __restrict__ X,
                                               const float* __restrict__ Wm,
                                               const float* __restrict__ bias,
                                               float* __restrict__ out, int O) {
    __shared__ float Xs[16][128];
    __shared__ float Ws[16][36];                  // 36: float4-aligned rows
    const int b   = blockIdx.z;
    const int o0  = blockIdx.y * 32;
    const int hw0 = blockIdx.x * 128;
    const int tid = threadIdx.x;
    const int hid = tid & 31;   // hw group (4 contiguous)
    const int oid = tid >> 5;   // o group (4 contiguous)

    const float* xb = X + (size_t)b * Cc * HW;
    float acc[4][4];
#pragma unroll
    for (int n = 0; n < 4; n++)
#pragma unroll
        for (int m = 0; m < 4; m++) acc[n][m] = 0.f;

    for (int c0 = 0; c0 < Cc; c0 += 16) {
        __syncthreads();
#pragma unroll
        for (int r = 0; r < 8; r++) {            // 16*128/256 = 8 per thread
            int idx = tid + r * 256;
            int cc = idx >> 7, h = idx & 127;
            Xs[cc][h] = xb[(size_t)(c0 + cc) * HW + hw0 + h];
        }
#pragma unroll
        for (int r = 0; r < 2; r++) {            // 16*32/256 = 2 per thread
            int idx = tid + r * 256;
            int cc = idx >> 5, o = idx & 31;
            Ws[cc][o] = Wm[(size_t)(o0 + o) * Cc + c0 + cc];
        }
        __syncthreads();
#pragma unroll
        for (int cc = 0; cc < 16; cc++) {
            float4 wv = *(const float4*)&Ws[cc][oid * 4];   // broadcast in warp
            float4 xv = *(const float4*)&Xs[cc][hid * 4];   // conflict-free
            float wa[4] = {wv.x, wv.y, wv.z, wv.w};
            float xa[4] = {xv.x, xv.y, xv.z, xv.w};
#pragma unroll
            for (int n = 0; n < 4; n++)
#pragma unroll
                for (int m = 0; m < 4; m++) acc[n][m] += wa[n] * xa[m];
        }
    }
#pragma unroll
    for (int n = 0; n < 4; n++) {
        int o = o0 + oid * 4 + n;
        float bi = bias[o];
        float4 res;
        res.x = acc[n][0] + bi;
        res.y = acc[n][1] + bi;
        res.z = acc[n][2] + bi;
        res.w = acc[n][3] + bi;
        *(float4*)&out[(size_t)b * O * HW + (size_t)o * HW + hw0 + hid * 4] = res;
    }
}

// ---------------- 2) fused energy rowmax/argmax (f32x2) --------------------
// energy[b,i,j] = sum_c k[b,c,i]*q[b,c,j]; per query j: max/argmax over i.
// grid (jtile=32, b=4, split=4); block 128 (one query per thread).
__global__ __launch_bounds__(128) void energy_argmax() {
    __shared__ float ks[32][128];
    const int b  = blockIdx.y;
    const int j  = blockIdx.x * 128 + threadIdx.x;
    const int sp = blockIdx.z;
    const float* qb = g_q + (size_t)b * C8 * HW;
    const float* kb = g_k + (size_t)b * C8 * HW;

    ull qr2[32];
#pragma unroll
    for (int c = 0; c < 32; c++) {
        float qv = qb[c * HW + j];
        qr2[c] = pack2(qv, qv);
    }

    float best = -FLT_MAX;
    int   barg = 0;
    const int i0base = sp * 1024;

    for (int it = 0; it < 8; it++) {
        int i0 = i0base + it * 128;
        __syncthreads();
#pragma unroll
        for (int c = 0; c < 32; c++) ks[c][threadIdx.x] = kb[c * HW + i0 + threadIdx.x];
        __syncthreads();
#pragma unroll 4
        for (int ii = 0; ii < 128; ii += 4) {
            ull a01 = 0ULL, a23 = 0ULL;
#pragma unroll
            for (int c = 0; c < 32; c++) {
                ulonglong2 kp = *(const ulonglong2*)&ks[c][ii];  // broadcast LDS.128
                fma2(a01, kp.x, qr2[c]);
                fma2(a23, kp.y, qr2[c]);
            }
            float e0, e1, e2, e3;
            unpack2(a01, e0, e1);
            unpack2(a23, e2, e3);
            if (e0 > best) { best = e0; barg = i0 + ii; }
            if (e1 > best) { best = e1; barg = i0 + ii + 1; }
            if (e2 > best) { best = e2; barg = i0 + ii + 2; }
            if (e3 > best) { best = e3; barg = i0 + ii + 3; }
        }
    }
    g_pmax[((size_t)b * 4 + sp) * HW + j] = best;
    g_parg[((size_t)b * 4 + sp) * HW + j] = barg;
}

// ---------------- 3) reduce the 4 key-splits (keeps lowest index on ties) --
__global__ void reduce_argmax() {
    int t = blockIdx.x * 256 + threadIdx.x;       // 16384
    if (t >= Bb * HW) return;
    int b = t >> 12, j = t & 4095;
    float best = g_pmax[((size_t)b * 4) * HW + j];
    int   arg  = g_parg[((size_t)b * 4) * HW + j];
#pragma unroll
    for (int sp = 1; sp < 4; sp++) {
        float e = g_pmax[((size_t)b * 4 + sp) * HW + j];
        if (e > best) { best = e; arg = g_parg[((size_t)b * 4 + sp) * HW + j]; }
    }
    g_S[t] = best;
    g_arg[t] = arg;
}

// ---------------- 4) gather T[b,c,p] = v[b,c,arg[b,p]] ---------------------
__global__ void gather_T() {
    int p = blockIdx.x * 256 + threadIdx.x;
    int c = blockIdx.y, b = blockIdx.z;
    int a = g_arg[b * HW + p];
    g_T[((size_t)b * Cc + c) * HW + p] = g_v[((size_t)b * Cc + c) * HW + a];
}

// ---------------- 5) conv3x3 over cat(front_x, T) + epilogue (f32x2) -------
// block: 64 output channels x 16x16 spatial, 256 threads, thread tile 8o x 8s.
// weights staged DUPLICATED as float2 -> packed operand is one broadcast LDS.64
__global__ __launch_bounds__(256, 2) void conv3x3_epi(const float* __restrict__ front_x,
                                                      const float* __restrict__ bf,
                                                      float* __restrict__ out) {
    __shared__ float  in_s[4][18][18];
    __shared__ float2 w2_s[4 * 9 * 64];           // 18 KB, duplicated pairs
    __shared__ float  S_s[256];

    const int b   = blockIdx.z;
    const int o0  = blockIdx.y * 64;
    const int st  = blockIdx.x;                  // 16 spatial tiles
    const int y0  = (st >> 2) * 16;
    const int x0  = (st & 3) * 16;
    const int tid = threadIdx.x;
    const int sid = tid & 31;                    // spatial lane
    const int oid = tid >> 5;                    // 0..7
    const int srow = sid >> 4;                   // 0/1
    const int scol = sid & 15;

    {
        int ry = tid >> 4, rx = tid & 15;
        S_s[tid] = g_S[(size_t)b * HW + (y0 + ry) * Ww + x0 + rx];
    }

    // acc2[n][p] packs spatial m=2p (lo), m=2p+1 (hi)
    ull acc2[8][4];
#pragma unroll
    for (int n = 0; n < 8; n++)
#pragma unroll
        for (int p = 0; p < 4; p++) acc2[n][p] = 0ULL;

    for (int ci0 = 0; ci0 < 512; ci0 += 4) {
        __syncthreads();
        // input tile 4 x 18 x 18, zero-padded
        for (int idx = tid; idx < 4 * 324; idx += 256) {
            int cil = idx / 324, rem = idx % 324;
            int r = rem / 18, cc = rem % 18;
            int ci = ci0 + cil;
            int y = y0 + r - 1, x = x0 + cc - 1;
            float v = 0.f;
            if (y >= 0 && y < Hh && x >= 0 && x < Ww) {
                const float* s = (ci < 256)
                    ? (front_x + ((size_t)b * Cc + ci) * HW)
                    : (g_T + ((size_t)b * Cc + (ci - 256)) * HW);
                v = s[y * Ww + x];
            }
            in_s[cil][r][cc] = v;
        }
        // weights (pre-transposed, coalesced), stored duplicated
#pragma unroll
        for (int r = 0; r < 9; r++) {            // 4*9*64/256 = 9 per thread
            int idx = tid + r * 256;
            float w = g_Wt[(size_t)(ci0 + (idx >> 6) / 9) * 9 * 256
                           + ((idx >> 6) % 9) * 256 + o0 + (idx & 63)];
            w2_s[idx] = make_float2(w, w);
        }
        __syncthreads();

        for (int cil = 0; cil < 4; cil++) {
#pragma unroll
            for (int k = 0; k < 9; k++) {
                const int ky = k / 3, kx = k % 3;
                ull wp[8];
#pragma unroll
                for (int n = 0; n < 8; n++)
                    wp[n] = *(const ull*)&w2_s[cil * 576 + k * 64 + oid + 8 * n];
                float iv[8];
#pragma unroll
                for (int m = 0; m < 8; m++)
                    iv[m] = in_s[cil][srow + 2 * m + ky][scol + kx];
                ull ip[4];
#pragma unroll
                for (int p = 0; p < 4; p++) ip[p] = pack2(iv[2 * p], iv[2 * p + 1]);
#pragma unroll
                for (int n = 0; n < 8; n++)
#pragma unroll
                    for (int p = 0; p < 4; p++) fma2(acc2[n][p], ip[p], wp[n]);
            }
        }
    }

    // epilogue: out = front_x + (conv + bf) * S
    float Sv[8];
#pragma unroll
    for (int m = 0; m < 8; m++) Sv[m] = S_s[(srow + 2 * m) * 16 + scol];
#pragma unroll
    for (int n = 0; n < 8; n++) {
        int o = o0 + oid + 8 * n;
        float bi = bf[o];
#pragma unroll
        for (int p = 0; p < 4; p++) {
            float alo, ahi;
            unpack2(acc2[n][p], alo, ahi);
            {
                int m = 2 * p;
                int y = y0 + srow + 2 * m, x = x0 + scol;
                size_t off = ((size_t)b * Cc + o) * HW + y * Ww + x;
                out[off] = front_x[off] + (alo + bi) * Sv[m];
            }
            {
                int m = 2 * p + 1;
                int y = y0 + srow + 2 * m, x = x0 + scol;
                size_t off = ((size_t)b * Cc + o) * HW + y * Ww + x;
                out[off] = front_x[off] + (ahi + bi) * Sv[m];
            }
        }
    }
}

// ---------------- launch --------------------------------------------------
extern "C" void kernel_launch(void* const* d_in, const int* in_sizes, int n_in,
                              void* d_out, int out_size) {
    const float* front_x     = (const float*)d_in[0];
    const float* cross_x     = (const float*)d_in[1];
    const float* front_x_hat = (const float*)d_in[2];
    const float* Wq = (const float*)d_in[3];
    const float* bq = (const float*)d_in[4];
    const float* Wk = (const float*)d_in[5];
    const float* bk = (const float*)d_in[6];
    const float* Wv = (const float*)d_in[7];
    const float* bv = (const float*)d_in[8];
    const float* Wf = (const float*)d_in[9];
    const float* bf = (const float*)d_in[10];
    float* out = (float*)d_out;

    float *q, *k, *v;
    cudaGetSymbolAddress((void**)&q, g_q);
    cudaGetSymbolAddress((void**)&k, g_k);
    cudaGetSymbolAddress((void**)&v, g_v);

    transpose_wf<<<4608, 256>>>(Wf);

    gemm1x1<<<dim3(32, 1, 4), 256>>>(cross_x,     Wq, bq, q, C8);   // q
    gemm1x1<<<dim3(32, 1, 4), 256>>>(front_x,     Wk, bk, k, C8);   // k
    gemm1x1<<<dim3(32, 8, 4), 256>>>(front_x_hat, Wv, bv, v, Cc);   // v

    energy_argmax<<<dim3(32, 4, 4), 128>>>();
    reduce_argmax<<<64, 256>>>();
    gather_T<<<dim3(16, 256, 4), 256>>>();

    conv3x3_epi<<<dim3(16, 4, 4), 256>>>(front_x, bf, out);
}

// round 4
// speedup vs baseline: 2.4917x; 2.4917x over previous
#include <cuda_runtime.h>
#include <cuda_bf16.h>
#include <float.h>
#include <stdint.h>

#define Bb 4
#define Cc 256
#define C8 32
#define Hh 64
#define Ww 64
#define HW 4096

// ===================== helpers =============================================
__device__ __forceinline__ uint32_t smem_u32(const void* p) {
    uint32_t a;
    asm("{ .reg .u64 t; cvta.to.shared.u64 t, %1; cvt.u32.u64 %0, t; }"
        : "=r"(a) : "l"(p));
    return a;
}
#define SWZ128(off) ((off) ^ (((off) >> 3) & 0x70))

__device__ __forceinline__ void ldsm_x4(uint32_t (&r)[4], uint32_t addr) {
    asm volatile("ldmatrix.sync.aligned.m8n8.x4.shared.b16 {%0,%1,%2,%3}, [%4];"
                 : "=r"(r[0]), "=r"(r[1]), "=r"(r[2]), "=r"(r[3]) : "r"(addr));
}

__device__ __forceinline__ void mma_bf16(float (&d)[4], const uint32_t (&a)[4],
                                         uint32_t b0, uint32_t b1) {
    asm volatile(
        "mma.sync.aligned.m16n8k16.row.col.f32.bf16.bf16.f32 "
        "{%0,%1,%2,%3}, {%4,%5,%6,%7}, {%8,%9}, {%0,%1,%2,%3};"
        : "+f"(d[0]), "+f"(d[1]), "+f"(d[2]), "+f"(d[3])
        : "r"(a[0]), "r"(a[1]), "r"(a[2]), "r"(a[3]), "r"(b0), "r"(b1));
}

#define CP_ASYNC16(dst, src) \
    asm volatile("cp.async.cg.shared.global [%0], [%1], 16;" :: "r"(dst), "l"(src) : "memory")
#define CP_COMMIT()  asm volatile("cp.async.commit_group;" ::: "memory")
#define CP_WAIT0()   asm volatile("cp.async.wait_group 0;" ::: "memory")

// ===================== scratch =============================================
__device__ float g_q[Bb * C8 * HW];
__device__ float g_k[Bb * C8 * HW];
__device__ float g_v[Bb * Cc * HW];
__device__ float g_T[Bb * Cc * HW];
__device__ float g_pmax[Bb * 4 * HW];
__device__ int   g_parg[Bb * 4 * HW];
__device__ float g_S[Bb * HW];
__device__ int   g_arg[Bb * HW];
// NHWC bf16, zero halo: [B][66][66][hi 512 | lo 512]
__device__ __nv_bfloat16 g_Xt[(size_t)Bb * 66 * 66 * 1024];
// weights split: [seg(hi0/lo1)][tap9][o 256][c 512] bf16
__device__ __nv_bfloat16 g_Wa[2 * 9 * 256 * 512];

// ===================== 1x1 GEMM (q,k,v projections) ========================
__global__ __launch_bounds__(256) void gemm1x1(const float* __restrict__ X,
                                               const float* __restrict__ Wm,
                                               const float* __restrict__ bias,
                                               float* __restrict__ out, int O) {
    __shared__ float Xs[16][128];
    __shared__ float Ws[16][36];
    const int b   = blockIdx.z;
    const int o0  = blockIdx.y * 32;
    const int hw0 = blockIdx.x * 128;
    const int tid = threadIdx.x;
    const int hid = tid & 31;
    const int oid = tid >> 5;

    const float* xb = X + (size_t)b * Cc * HW;
    float acc[4][4];
#pragma unroll
    for (int n = 0; n < 4; n++)
#pragma unroll
        for (int m = 0; m < 4; m++) acc[n][m] = 0.f;

    for (int c0 = 0; c0 < Cc; c0 += 16) {
        __syncthreads();
#pragma unroll
        for (int r = 0; r < 8; r++) {
            int idx = tid + r * 256;
            int cc = idx >> 7, h = idx & 127;
            Xs[cc][h] = xb[(size_t)(c0 + cc) * HW + hw0 + h];
        }
#pragma unroll
        for (int r = 0; r < 2; r++) {
            int idx = tid + r * 256;
            int cc = idx >> 5, o = idx & 31;
            Ws[cc][o] = Wm[(size_t)(o0 + o) * Cc + c0 + cc];
        }
        __syncthreads();
#pragma unroll
        for (int cc = 0; cc < 16; cc++) {
            float4 wv = *(const float4*)&Ws[cc][oid * 4];
            float4 xv = *(const float4*)&Xs[cc][hid * 4];
            float wa[4] = {wv.x, wv.y, wv.z, wv.w};
            float xa[4] = {xv.x, xv.y, xv.z, xv.w};
#pragma unroll
            for (int n = 0; n < 4; n++)
#pragma unroll
                for (int m = 0; m < 4; m++) acc[n][m] += wa[n] * xa[m];
        }
    }
#pragma unroll
    for (int n = 0; n < 4; n++) {
        int o = o0 + oid * 4 + n;
        float bi = bias[o];
        float4 res;
        res.x = acc[n][0] + bi;
        res.y = acc[n][1] + bi;
        res.z = acc[n][2] + bi;
        res.w = acc[n][3] + bi;
        *(float4*)&out[(size_t)b * O * HW + (size_t)o * HW + hw0 + hid * 4] = res;
    }
}

// ===================== energy rowmax/argmax (exact fp32) ====================
__global__ __launch_bounds__(128) void energy_argmax() {
    __shared__ float ks[32][128];
    const int b  = blockIdx.y;
    const int j  = blockIdx.x * 128 + threadIdx.x;
    const int sp = blockIdx.z;
    const float* qb = g_q + (size_t)b * C8 * HW;
    const float* kb = g_k + (size_t)b * C8 * HW;

    float qr[32];
#pragma unroll
    for (int c = 0; c < 32; c++) qr[c] = qb[c * HW + j];

    float best = -FLT_MAX;
    int   barg = 0;
    const int i0base = sp * 1024;

    for (int it = 0; it < 8; it++) {
        int i0 = i0base + it * 128;
        __syncthreads();
#pragma unroll
        for (int c = 0; c < 32; c++) ks[c][threadIdx.x] = kb[c * HW + i0 + threadIdx.x];
        __syncthreads();
#pragma unroll 4
        for (int ii = 0; ii < 128; ii += 4) {
            float a0 = 0.f, a1 = 0.f, a2 = 0.f, a3 = 0.f;
#pragma unroll
            for (int c = 0; c < 32; c++) {
                float4 kv = *(const float4*)&ks[c][ii];
                a0 += kv.x * qr[c];
                a1 += kv.y * qr[c];
                a2 += kv.z * qr[c];
                a3 += kv.w * qr[c];
            }
            if (a0 > best) { best = a0; barg = i0 + ii; }
            if (a1 > best) { best = a1; barg = i0 + ii + 1; }
            if (a2 > best) { best = a2; barg = i0 + ii + 2; }
            if (a3 > best) { best = a3; barg = i0 + ii + 3; }
        }
    }
    g_pmax[((size_t)b * 4 + sp) * HW + j] = best;
    g_parg[((size_t)b * 4 + sp) * HW + j] = barg;
}

__global__ void reduce_argmax() {
    int t = blockIdx.x * 256 + threadIdx.x;
    if (t >= Bb * HW) return;
    int b = t >> 12, j = t & 4095;
    float best = g_pmax[((size_t)b * 4) * HW + j];
    int   arg  = g_parg[((size_t)b * 4) * HW + j];
#pragma unroll
    for (int sp = 1; sp < 4; sp++) {
        float e = g_pmax[((size_t)b * 4 + sp) * HW + j];
        if (e > best) { best = e; arg = g_parg[((size_t)b * 4 + sp) * HW + j]; }
    }
    g_S[t] = best;
    g_arg[t] = arg;
}

__global__ void gather_T() {
    int p = blockIdx.x * 256 + threadIdx.x;
    int c = blockIdx.y, b = blockIdx.z;
    int a = g_arg[b * HW + p];
    g_T[((size_t)b * Cc + c) * HW + p] = g_v[((size_t)b * Cc + c) * HW + a];
}

// ===================== conv input prep (NHWC bf16 hi/lo + halo) ============
__global__ void zero_xt() {
    size_t i = (size_t)blockIdx.x * 256 + threadIdx.x;   // uint4 units
    ((uint4*)g_Xt)[i] = make_uint4(0, 0, 0, 0);
}

__global__ __launch_bounds__(256) void fill_xt(const float* __restrict__ front_x) {
    __shared__ float sm[32][65];
    const int c0 = blockIdx.x * 32;      // 16 chunks of 32 channels (0..511)
    const int y  = blockIdx.y;
    const int b  = blockIdx.z;
    const int tid = threadIdx.x;

#pragma unroll
    for (int pass = 0; pass < 8; pass++) {
        int idx = tid + pass * 256;
        int cc = idx >> 6, x = idx & 63;
        int c = c0 + cc;
        float v;
        if (c < 256)
            v = front_x[((size_t)b * Cc + c) * HW + y * Ww + x];
        else
            v = g_T[((size_t)b * Cc + (c - 256)) * HW + y * Ww + x];
        sm[cc][x] = v;
    }
    __syncthreads();

    int x = tid >> 2, g = tid & 3;
    uint32_t hu[4], lu[4];
#pragma unroll
    for (int e = 0; e < 4; e++) {
        float v0 = sm[g * 8 + e * 2][x];
        float v1 = sm[g * 8 + e * 2 + 1][x];
        __nv_bfloat16 h0 = __float2bfloat16_rn(v0);
        __nv_bfloat16 h1 = __float2bfloat16_rn(v1);
        __nv_bfloat16 l0 = __float2bfloat16_rn(v0 - __bfloat162float(h0));
        __nv_bfloat16 l1 = __float2bfloat16_rn(v1 - __bfloat162float(h1));
        hu[e] = (uint32_t)__bfloat16_as_ushort(h0) | ((uint32_t)__bfloat16_as_ushort(h1) << 16);
        lu[e] = (uint32_t)__bfloat16_as_ushort(l0) | ((uint32_t)__bfloat16_as_ushort(l1) << 16);
    }
    size_t base = ((size_t)(b * 66 + y + 1) * 66 + (x + 1)) * 1024 + c0 + g * 8;
    *(uint4*)&g_Xt[base]       = make_uint4(hu[0], hu[1], hu[2], hu[3]);
    *(uint4*)&g_Xt[base + 512] = make_uint4(lu[0], lu[1], lu[2], lu[3]);
}

// weights: Wf(O=256, I=512, 3,3) -> g_Wa[seg][tap][o][i] bf16 hi/lo
__global__ void prep_w(const float* __restrict__ Wf) {
    int t = blockIdx.x * 256 + threadIdx.x;       // 131072
    int o = t >> 9, i = t & 511;
#pragma unroll
    for (int k = 0; k < 9; k++) {
        float w = Wf[((size_t)o * 512 + i) * 9 + k];
        __nv_bfloat16 h = __float2bfloat16_rn(w);
        __nv_bfloat16 l = __float2bfloat16_rn(w - __bfloat162float(h));
        g_Wa[(((size_t)0 * 9 + k) * 256 + o) * 512 + i] = h;
        g_Wa[(((size_t)1 * 9 + k) * 256 + o) * 512 + i] = l;
    }
}

// ===================== mma.sync conv3x3 + fused epilogue ====================
// CTA: M=128 out-ch x N=128 px (2 rows). 8 warps = 4(M) x 2(N), warp 32x64.
// K loop: 9 taps x 8 chunks of 64ch. Stage/chunk: 4 SW128 tiles of 128x64 bf16
// (Bhi, Blo, Ahi, Alo; 16KB each) via cp.async, double-buffered.
#define STAGE 65536
#define NCHUNK 72

__device__ __forceinline__ void stage_chunk(uint32_t stg, int s, int b, int y0, int m0) {
    const int tap = s >> 3, kc = (s & 7) * 64;
    const int dy = tap / 3, dx = tap % 3;
    const int tid = threadIdx.x;
#pragma unroll
    for (int i = 0; i < 16; i++) {
        const int t = i >> 2;                         // 0:Bhi 1:Blo 2:Ahi 3:Alo
        const int c = ((i & 3) << 8) + tid;           // 0..1023
        const int r = c >> 3, c16 = c & 7;
        uint32_t dst = stg + (uint32_t)(t * 16384) + SWZ128((uint32_t)(r * 128 + c16 * 16));
        const void* src;
        if (t < 2) {
            const int ry = r >> 6, x = r & 63;
            src = &g_Xt[(((size_t)(b * 66 + y0 + ry + dy) * 66) + (x + dx)) * 1024
                        + t * 512 + kc + c16 * 8];
        } else {
            src = &g_Wa[(((size_t)((t - 2) * 9 + tap) * 256) + m0 + r) * 512 + kc + c16 * 8];
        }
        CP_ASYNC16(dst, src);
    }
    CP_COMMIT();
}

__global__ __launch_bounds__(256, 1) void conv_mma(const float* __restrict__ front_x,
                                                   const float* __restrict__ bf,
                                                   float* __restrict__ out) {
    extern __shared__ char dynsm[];
    const int tid  = threadIdx.x;
    const int lane = tid & 31;
    const int wid  = tid >> 5;
    const int wm   = wid & 3;                 // M warp (0..3) -> 32 rows
    const int wn   = wid >> 2;                // N warp (0..1) -> 64 px
    const int nt   = blockIdx.x;              // 32 pixel tiles
    const int m0   = blockIdx.y * 128;        // out-ch half
    const int b    = blockIdx.z;
    const int y0   = nt * 2;
    const int n0   = nt * 128;

    const uint32_t smbase = smem_u32(dynsm);

    float acc[2][8][4];
#pragma unroll
    for (int mt = 0; mt < 2; mt++)
#pragma unroll
        for (int j = 0; j < 8; j++)
#pragma unroll
            for (int e = 0; e < 4; e++) acc[mt][j][e] = 0.f;

    const int arow  = wm * 32 + (lane & 15);
    const int acolh = (lane >> 4) * 16;
    const int brow  = wn * 64 + (lane & 7) + ((lane >> 4) << 3);
    const int bcolh = ((lane >> 3) & 1) * 16;

    stage_chunk(smbase, 0, b, y0, m0);

    for (int s = 0; s < NCHUNK; s++) {
        CP_WAIT0();
        __syncthreads();
        if (s + 1 < NCHUNK)
            stage_chunk(smbase + ((s + 1) & 1) * STAGE, s + 1, b, y0, m0);

        const uint32_t base = smbase + (s & 1) * STAGE;
        const uint32_t tBhi = base, tBlo = base + 16384;
        const uint32_t tAhi = base + 32768, tAlo = base + 49152;

#pragma unroll
        for (int ks = 0; ks < 4; ks++) {
            uint32_t ah[2][4], al[2][4], bh[4][4], bl[4][4];
#pragma unroll
            for (int mt = 0; mt < 2; mt++) {
                uint32_t off = SWZ128((uint32_t)((arow + mt * 16) * 128 + ks * 32 + acolh));
                ldsm_x4(ah[mt], tAhi + off);
                ldsm_x4(al[mt], tAlo + off);
            }
#pragma unroll
            for (int j = 0; j < 4; j++) {
                uint32_t off = SWZ128((uint32_t)((brow + j * 16) * 128 + ks * 32 + bcolh));
                ldsm_x4(bh[j], tBhi + off);
                ldsm_x4(bl[j], tBlo + off);
            }
#pragma unroll
            for (int mt = 0; mt < 2; mt++)
#pragma unroll
                for (int j = 0; j < 4; j++) {
                    mma_bf16(acc[mt][2 * j],     ah[mt], bh[j][0], bh[j][1]);
                    mma_bf16(acc[mt][2 * j + 1], ah[mt], bh[j][2], bh[j][3]);
                    mma_bf16(acc[mt][2 * j],     al[mt], bh[j][0], bh[j][1]);
                    mma_bf16(acc[mt][2 * j + 1], al[mt], bh[j][2], bh[j][3]);
                    mma_bf16(acc[mt][2 * j],     ah[mt], bl[j][0], bl[j][1]);
                    mma_bf16(acc[mt][2 * j + 1], ah[mt], bl[j][2], bl[j][3]);
                }
        }
        __syncthreads();
    }

    // fused epilogue: out = front_x + (conv + bf) * S, direct register stores
    const float* Sb = g_S + (size_t)b * HW;
#pragma unroll
    for (int mt = 0; mt < 2; mt++) {
        const int o_lo = m0 + wm * 32 + mt * 16 + (lane >> 2);
        const int o_hi = o_lo + 8;
        const float bi_lo = bf[o_lo], bi_hi = bf[o_hi];
#pragma unroll
        for (int j = 0; j < 8; j++) {
            const int p = n0 + wn * 64 + j * 8 + 2 * (lane & 3);
            const float2 Sv = *(const float2*)&Sb[p];
            const size_t off0 = ((size_t)(b * Cc + o_lo)) * HW + p;
            const size_t off1 = ((size_t)(b * Cc + o_hi)) * HW + p;
            const float2 f0 = *(const float2*)&front_x[off0];
            const float2 f1 = *(const float2*)&front_x[off1];
            float2 r0, r1;
            r0.x = f0.x + (acc[mt][j][0] + bi_lo) * Sv.x;
            r0.y = f0.y + (acc[mt][j][1] + bi_lo) * Sv.y;
            r1.x = f1.x + (acc[mt][j][2] + bi_hi) * Sv.x;
            r1.y = f1.y + (acc[mt][j][3] + bi_hi) * Sv.y;
            *(float2*)&out[off0] = r0;
            *(float2*)&out[off1] = r1;
        }
    }
}

// ===================== launch ==============================================
extern "C" void kernel_launch(void* const* d_in, const int* in_sizes, int n_in,
                              void* d_out, int out_size) {
    const float* front_x     = (const float*)d_in[0];
    const float* cross_x     = (const float*)d_in[1];
    const float* front_x_hat = (const float*)d_in[2];
    const float* Wq = (const float*)d_in[3];
    const float* bq = (const float*)d_in[4];
    const float* Wk = (const float*)d_in[5];
    const float* bk = (const float*)d_in[6];
    const float* Wv = (const float*)d_in[7];
    const float* bv = (const float*)d_in[8];
    const float* Wf = (const float*)d_in[9];
    const float* bf = (const float*)d_in[10];
    float* out = (float*)d_out;

    cudaFuncSetAttribute(conv_mma, cudaFuncAttributeMaxDynamicSharedMemorySize, 2 * STAGE);

    float *q, *k, *v;
    cudaGetSymbolAddress((void**)&q, g_q);
    cudaGetSymbolAddress((void**)&k, g_k);
    cudaGetSymbolAddress((void**)&v, g_v);

    zero_xt<<<8712, 256>>>();
    prep_w<<<512, 256>>>(Wf);

    gemm1x1<<<dim3(32, 1, 4), 256>>>(cross_x,     Wq, bq, q, C8);
    gemm1x1<<<dim3(32, 1, 4), 256>>>(front_x,     Wk, bk, k, C8);
    gemm1x1<<<dim3(32, 8, 4), 256>>>(front_x_hat, Wv, bv, v, Cc);

    energy_argmax<<<dim3(32, 4, 4), 128>>>();
    reduce_argmax<<<64, 256>>>();
    gather_T<<<dim3(16, 256, 4), 256>>>();

    fill_xt<<<dim3(16, 64, 4), 256>>>(front_x);

    conv_mma<<<dim3(32, 2, 4), 256, 2 * STAGE>>>(front_x, bf, out);
}